// round 7
// baseline (speedup 1.0000x reference)
#include <cuda_runtime.h>

#define NB 256
#define NT 1024
#define NL 64

__device__ float g_norm[NB];
__device__ float g_gold2[2][NB];

__device__ __forceinline__ float warp_sum(float v) {
#pragma unroll
    for (int k = 16; k; k >>= 1) v += __shfl_xor_sync(0xffffffffu, v, k);
    return v;
}

// One time step for BOTH batches (A,B) handled by this warp, fully interleaved.
// Reads u(t-1) from buf[RD], writes u(t) to buf[RD^1]. Lane owns states 2l, 2l+1.
// The two chains are independent -> their FMA streams hide each other's latency.
#define CRF_STEP2(RD, eA, eB, RESC) do {                                                \
    const float eeA0_ = __expf((eA).x), eeA1_ = __expf((eA).y);                         \
    const float eeB0_ = __expf((eB).x), eeB1_ = __expf((eB).y);                         \
    const float* rA_ = usm[0][(RD)];                                                    \
    const float* rB_ = usm[1][(RD)];                                                    \
    float rrA_ = 1.0f, rrB_ = 1.0f;                                                     \
    if (RESC) {                                                                         \
        const float uA0_ = rA_[0], uB0_ = rB_[0];                                       \
        asm("rcp.approx.f32 %0, %1;" : "=f"(rrA_) : "f"(uA0_));                         \
        asm("rcp.approx.f32 %0, %1;" : "=f"(rrB_) : "f"(uB0_));                         \
        MacA += (double)__logf(uA0_);                                                   \
        MacB += (double)__logf(uB0_);                                                   \
    }                                                                                   \
    unsigned long long aA0_=0ull, aA1_=0ull, aA2_=0ull, aA3_=0ull;                      \
    unsigned long long aB0_=0ull, aB1_=0ull, aB2_=0ull, aB3_=0ull;                      \
    const ulonglong2* rpA_ = (const ulonglong2*)rA_;                                    \
    const ulonglong2* rpB_ = (const ulonglong2*)rB_;                                    \
    _Pragma("unroll")                                                                   \
    for (int j_ = 0; j_ < 16; j_++) {                                                   \
        const ulonglong2 vA_ = rpA_[j_];                                                \
        const ulonglong2 vB_ = rpB_[j_];                                                \
        asm("fma.rn.f32x2 %0, %1, %2, %0;" : "+l"(aA0_) : "l"(vA_.x), "l"(E0[2*j_]));   \
        asm("fma.rn.f32x2 %0, %1, %2, %0;" : "+l"(aB0_) : "l"(vB_.x), "l"(E0[2*j_]));   \
        asm("fma.rn.f32x2 %0, %1, %2, %0;" : "+l"(aA1_) : "l"(vA_.y), "l"(E0[2*j_+1])); \
        asm("fma.rn.f32x2 %0, %1, %2, %0;" : "+l"(aB1_) : "l"(vB_.y), "l"(E0[2*j_+1])); \
        asm("fma.rn.f32x2 %0, %1, %2, %0;" : "+l"(aA2_) : "l"(vA_.x), "l"(E1[2*j_]));   \
        asm("fma.rn.f32x2 %0, %1, %2, %0;" : "+l"(aB2_) : "l"(vB_.x), "l"(E1[2*j_]));   \
        asm("fma.rn.f32x2 %0, %1, %2, %0;" : "+l"(aA3_) : "l"(vA_.y), "l"(E1[2*j_+1])); \
        asm("fma.rn.f32x2 %0, %1, %2, %0;" : "+l"(aB3_) : "l"(vB_.y), "l"(E1[2*j_+1])); \
    }                                                                                   \
    asm("add.rn.f32x2 %0, %0, %1;" : "+l"(aA0_) : "l"(aA1_));                           \
    asm("add.rn.f32x2 %0, %0, %1;" : "+l"(aA2_) : "l"(aA3_));                           \
    asm("add.rn.f32x2 %0, %0, %1;" : "+l"(aB0_) : "l"(aB1_));                           \
    asm("add.rn.f32x2 %0, %0, %1;" : "+l"(aB2_) : "l"(aB3_));                           \
    float xA0_, yA0_, xA1_, yA1_, xB0_, yB0_, xB1_, yB1_;                               \
    asm("mov.b64 {%0, %1}, %2;" : "=f"(xA0_), "=f"(yA0_) : "l"(aA0_));                  \
    asm("mov.b64 {%0, %1}, %2;" : "=f"(xA1_), "=f"(yA1_) : "l"(aA2_));                  \
    asm("mov.b64 {%0, %1}, %2;" : "=f"(xB0_), "=f"(yB0_) : "l"(aB0_));                  \
    asm("mov.b64 {%0, %1}, %2;" : "=f"(xB1_), "=f"(yB1_) : "l"(aB2_));                  \
    if (RESC) {                                                                         \
        uA0r = (xA0_ + yA0_) * eeA0_ * rrA_; uA1r = (xA1_ + yA1_) * eeA1_ * rrA_;       \
        uB0r = (xB0_ + yB0_) * eeB0_ * rrB_; uB1r = (xB1_ + yB1_) * eeB1_ * rrB_;       \
    } else {                                                                            \
        uA0r = (xA0_ + yA0_) * eeA0_;        uA1r = (xA1_ + yA1_) * eeA1_;              \
        uB0r = (xB0_ + yB0_) * eeB0_;        uB1r = (xB1_ + yB1_) * eeB1_;              \
    }                                                                                   \
    unsigned long long upA_, upB_;                                                      \
    asm("mov.b64 %0, {%1, %2};" : "=l"(upA_) : "f"(uA0r), "f"(uA1r));                   \
    asm("mov.b64 %0, {%1, %2};" : "=l"(upB_) : "f"(uB0r), "f"(uB1r));                   \
    ((unsigned long long*)usm[0][(RD) ^ 1])[l] = upA_;                                  \
    ((unsigned long long*)usm[1][(RD) ^ 1])[l] = upB_;                                  \
    __syncwarp();                                                                       \
} while (0)

__global__ __launch_bounds__(32, 1) void crf_main_kernel(
    const float* __restrict__ scores, const int* __restrict__ targets,
    const float* __restrict__ startv, const float* __restrict__ Tmat,
    const float* __restrict__ endv)
{
    // ------------- gold-path CTAs (blockIdx 128..143): half-chains -------------
    if (blockIdx.x >= NB / 2) {
        const int idx  = (blockIdx.x - NB / 2) * 32 + threadIdx.x;  // 0..511
        const int b    = idx & (NB - 1);
        const int half = idx >> 8;
        const int*   tg = targets + (size_t)b * NT;
        const float* sc = scores + (size_t)b * NT * NL;
        float g; int tp, tbeg;
        if (half == 0) { tp = tg[0]; g = startv[tp] + sc[tp]; tbeg = 1; }
        else           { tp = tg[NT / 2 - 1]; g = 0.0f; tbeg = NT / 2; }
        const int tend = half ? NT : NT / 2;
#pragma unroll 8
        for (int t = tbeg; t < tend; t++) {
            const int c = tg[t];
            g += sc[(size_t)t * NL + c] + Tmat[c * NL + tp];
            tp = c;
        }
        if (half) g += endv[tp];
        g_gold2[half][b] = g;
        return;
    }

    // ------------- forward CTAs: ONE warp advances TWO batch chains -------------
    __shared__ __align__(16) float usm[2][2][NL];   // [batch][parity][state]

    const int l  = threadIdx.x;          // lane
    const int bA = blockIdx.x * 2;
    const int bB = bA + 1;
    const int o0 = 2 * l, o1 = 2 * l + 1;

    // E rows for this lane's two output states: E[o][k] = exp(T_mat[o][k]) (shared by A/B)
    unsigned long long E0[32], E1[32];
#pragma unroll
    for (int j = 0; j < 32; j++) {
        const float a0 = __expf(__ldg(&Tmat[o0 * NL + 2 * j]));
        const float a1 = __expf(__ldg(&Tmat[o0 * NL + 2 * j + 1]));
        asm("mov.b64 %0, {%1, %2};" : "=l"(E0[j]) : "f"(a0), "f"(a1));
        const float c0 = __expf(__ldg(&Tmat[o1 * NL + 2 * j]));
        const float c1 = __expf(__ldg(&Tmat[o1 * NL + 2 * j + 1]));
        asm("mov.b64 %0, {%1, %2};" : "=l"(E1[j]) : "f"(c0), "f"(c1));
    }

    const float2* sbA = reinterpret_cast<const float2*>(scores + (size_t)bA * NT * NL) + l;
    const float2* sbB = reinterpret_cast<const float2*>(scores + (size_t)bB * NT * NL) + l;

    // ---- t = 0 init, both chains ----
    const float2 emA = sbA[0];
    const float2 emB = sbB[0];
    const float s0 = startv[o0], s1 = startv[o1];
    const float pAx = s0 + emA.x, pAy = s1 + emA.y;
    const float pBx = s0 + emB.x, pBy = s1 + emB.y;
    const float mA = __shfl_sync(0xffffffffu, pAx, 0);
    const float mB = __shfl_sync(0xffffffffu, pBx, 0);
    double MacA = (double)mA, MacB = (double)mB;

    float uA0r = __expf(pAx - mA), uA1r = __expf(pAy - mA);
    float uB0r = __expf(pBx - mB), uB1r = __expf(pBy - mB);
    {
        unsigned long long upA, upB;
        asm("mov.b64 %0, {%1, %2};" : "=l"(upA) : "f"(uA0r), "f"(uA1r));
        asm("mov.b64 %0, {%1, %2};" : "=l"(upB) : "f"(uB0r), "f"(uB1r));
        ((unsigned long long*)usm[0][0])[l] = upA;
        ((unsigned long long*)usm[1][0])[l] = upB;
    }
    __syncwarp();

    // emit prefetch, depth 4 per chain
    float2 eA0 = sbA[1 * 32], eA1 = sbA[2 * 32], eA2 = sbA[3 * 32], eA3 = sbA[4 * 32];
    float2 eB0 = sbB[1 * 32], eB1 = sbB[2 * 32], eB2 = sbB[3 * 32], eB3 = sbB[4 * 32];

#pragma unroll 1
    for (int t = 1; t <= NT - 7; t += 4) {   // covers t = 1..1020
        CRF_STEP2(0, eA0, eB0, 1);
        eA0 = sbA[(size_t)(t + 4) * 32]; eB0 = sbB[(size_t)(t + 4) * 32];
        CRF_STEP2(1, eA1, eB1, 0);
        eA1 = sbA[(size_t)(t + 5) * 32]; eB1 = sbB[(size_t)(t + 5) * 32];
        CRF_STEP2(0, eA2, eB2, 0);
        eA2 = sbA[(size_t)(t + 6) * 32]; eB2 = sbB[(size_t)(t + 6) * 32];
        CRF_STEP2(1, eA3, eB3, 0);
        if (t + 7 <= NT - 1) { eA3 = sbA[(size_t)(t + 7) * 32]; eB3 = sbB[(size_t)(t + 7) * 32]; }
        else                 { eA3 = make_float2(0.f, 0.f);     eB3 = make_float2(0.f, 0.f); }
    }
    CRF_STEP2(0, eA0, eB0, 0);   // t = 1021
    CRF_STEP2(1, eA1, eB1, 0);   // t = 1022
    CRF_STEP2(0, eA2, eB2, 0);   // t = 1023

    // ---- finalize both chains: normalizer = Mac + log(sum u * e^end) ----
    const float w0 = __expf(endv[o0]), w1 = __expf(endv[o1]);
    const float sA = warp_sum(uA0r * w0 + uA1r * w1);
    const float sB = warp_sum(uB0r * w0 + uB1r * w1);
    if (l == 0) {
        g_norm[bA] = (float)(MacA + (double)__logf(sA));
        g_norm[bB] = (float)(MacB + (double)__logf(sB));
    }
}

__global__ void crf_reduce_kernel(float* __restrict__ out) {
    __shared__ float w[8];
    const int i = threadIdx.x;
    float v = g_norm[i] - g_gold2[0][i] - g_gold2[1][i];
#pragma unroll
    for (int k = 16; k; k >>= 1) v += __shfl_xor_sync(0xffffffffu, v, k);
    if ((i & 31) == 0) w[i >> 5] = v;
    __syncthreads();
    if (i == 0) {
        float s = 0.0f;
#pragma unroll
        for (int k = 0; k < 8; k++) s += w[k];
        out[0] = s * (1.0f / (float)NB);
    }
}

extern "C" void kernel_launch(void* const* d_in, const int* in_sizes, int n_in,
                              void* d_out, int out_size)
{
    const float* scores  = (const float*)d_in[0];
    const int*   targets = (const int*)d_in[1];
    const float* startv  = (const float*)d_in[2];
    const float* Tmat    = (const float*)d_in[3];
    const float* endv    = (const float*)d_in[4];

    crf_main_kernel<<<NB / 2 + 16, 32>>>(scores, targets, startv, Tmat, endv);
    crf_reduce_kernel<<<1, NB>>>((float*)d_out);
}

// round 8
// speedup vs baseline: 1.0677x; 1.0677x over previous
#include <cuda_runtime.h>

#define NB 256
#define NT 1024
#define NL 64

__device__ float g_norm[NB];
__device__ float g_gold2[2][NB];

__device__ __forceinline__ float warp_sum(float v) {
#pragma unroll
    for (int k = 16; k; k >>= 1) v += __shfl_xor_sync(0xffffffffu, v, k);
    return v;
}

// One scan step, intra-warp. Reads u(t-1) from buf[RD], writes u(t) to buf[RD^1].
// Lane owns output states 2l, 2l+1. E rows in regs as f32x2. Plain (non-volatile)
// smem ops ordered by __syncwarp so ptxas can front-batch the broadcast loads.
#define CRF_STEP(RD, epk, RESC) do {                                                   \
    const float ee0_ = __expf((epk).x);                                                \
    const float ee1_ = __expf((epk).y);                                                \
    const float* rbuf_ = usw[(RD)];                                                    \
    float r_ = 1.0f;                                                                   \
    if (RESC) {                                                                        \
        const float u0_ = rbuf_[0];                                                    \
        asm("rcp.approx.f32 %0, %1;" : "=f"(r_) : "f"(u0_));                           \
        Mac += (double)__logf(u0_);                                                    \
    }                                                                                  \
    unsigned long long a0_ = 0ull, a1_ = 0ull, a2_ = 0ull, a3_ = 0ull;                 \
    const ulonglong2* rp_ = (const ulonglong2*)rbuf_;                                  \
    _Pragma("unroll")                                                                  \
    for (int j_ = 0; j_ < 16; j_++) {                                                  \
        const ulonglong2 v_ = rp_[j_];                                                 \
        asm("fma.rn.f32x2 %0, %1, %2, %0;" : "+l"(a0_) : "l"(v_.x), "l"(E0[2*j_]));    \
        asm("fma.rn.f32x2 %0, %1, %2, %0;" : "+l"(a1_) : "l"(v_.y), "l"(E0[2*j_+1]));  \
        asm("fma.rn.f32x2 %0, %1, %2, %0;" : "+l"(a2_) : "l"(v_.x), "l"(E1[2*j_]));    \
        asm("fma.rn.f32x2 %0, %1, %2, %0;" : "+l"(a3_) : "l"(v_.y), "l"(E1[2*j_+1]));  \
    }                                                                                  \
    asm("add.rn.f32x2 %0, %0, %1;" : "+l"(a0_) : "l"(a1_));                            \
    asm("add.rn.f32x2 %0, %0, %1;" : "+l"(a2_) : "l"(a3_));                            \
    float x0_, y0_, x1_, y1_;                                                          \
    asm("mov.b64 {%0, %1}, %2;" : "=f"(x0_), "=f"(y0_) : "l"(a0_));                    \
    asm("mov.b64 {%0, %1}, %2;" : "=f"(x1_), "=f"(y1_) : "l"(a2_));                    \
    if (RESC) { u0r = (x0_ + y0_) * ee0_ * r_; u1r = (x1_ + y1_) * ee1_ * r_; }        \
    else      { u0r = (x0_ + y0_) * ee0_;      u1r = (x1_ + y1_) * ee1_; }             \
    unsigned long long up_;                                                            \
    asm("mov.b64 %0, {%1, %2};" : "=l"(up_) : "f"(u0r), "f"(u1r));                     \
    ((unsigned long long*)usw[(RD) ^ 1])[l] = up_;                                     \
    __syncwarp();                                                                      \
} while (0)

__global__ __launch_bounds__(256, 1) void crf_main_kernel(
    const float* __restrict__ scores, const int* __restrict__ targets,
    const float* __restrict__ startv, const float* __restrict__ Tmat,
    const float* __restrict__ endv)
{
    // ---- gold-path CTAs (blockIdx 32..33): 512 half-chains, one per thread ----
    if (blockIdx.x >= 32) {
        const int idx  = (blockIdx.x - 32) * 256 + threadIdx.x;  // 0..511
        const int b    = idx & (NB - 1);
        const int half = idx >> 8;
        const int*   tg = targets + (size_t)b * NT;
        const float* sc = scores + (size_t)b * NT * NL;
        float g; int tp, tbeg;
        if (half == 0) { tp = tg[0]; g = startv[tp] + sc[tp]; tbeg = 1; }
        else           { tp = tg[NT / 2 - 1]; g = 0.0f; tbeg = NT / 2; }
        const int tend = half ? NT : NT / 2;
#pragma unroll 8
        for (int t = tbeg; t < tend; t++) {
            const int c = tg[t];
            g += sc[(size_t)t * NL + c] + Tmat[c * NL + tp];
            tp = c;
        }
        if (half) g += endv[tp];
        g_gold2[half][b] = g;
        return;
    }

    // ---- forward CTAs: 8 warps = 8 chains; 2 warps per SMSP hide each other ----
    __shared__ __align__(16) float usm[8][2][NL];   // [warp][parity][state]

    const int w  = threadIdx.x >> 5;     // warp in CTA -> SMSP w%4, 2 warps/SMSP
    const int l  = threadIdx.x & 31;
    const int b  = blockIdx.x * 8 + w;   // one batch chain per warp
    const int o0 = 2 * l, o1 = 2 * l + 1;
    float (*usw)[NL] = usm[w];

    // E rows for this lane's two output states: E[o][k] = exp(T_mat[o][k])
    unsigned long long E0[32], E1[32];
#pragma unroll
    for (int j = 0; j < 32; j++) {
        const float a0 = __expf(__ldg(&Tmat[o0 * NL + 2 * j]));
        const float a1 = __expf(__ldg(&Tmat[o0 * NL + 2 * j + 1]));
        asm("mov.b64 %0, {%1, %2};" : "=l"(E0[j]) : "f"(a0), "f"(a1));
        const float c0 = __expf(__ldg(&Tmat[o1 * NL + 2 * j]));
        const float c1 = __expf(__ldg(&Tmat[o1 * NL + 2 * j + 1]));
        asm("mov.b64 %0, {%1, %2};" : "=l"(E1[j]) : "f"(c0), "f"(c1));
    }

    // ---- t = 0 init ----
    const float2* sb2 = reinterpret_cast<const float2*>(scores + (size_t)b * NT * NL) + l;
    const float2 em0 = sb2[0];
    const float p0x = startv[o0] + em0.x;
    const float p0y = startv[o1] + em0.y;
    const float m0  = __shfl_sync(0xffffffffu, p0x, 0);   // anchor = prev0[state 0]
    double Mac = (double)m0;

    float u0r = __expf(p0x - m0);
    float u1r = __expf(p0y - m0);
    {
        unsigned long long up;
        asm("mov.b64 %0, {%1, %2};" : "=l"(up) : "f"(u0r), "f"(u1r));
        ((unsigned long long*)usw[0])[l] = up;            // buf 0 = u(0)
    }
    __syncwarp();

    // emit prefetch, depth 4
    float2 e0p = sb2[1 * 32];
    float2 e1p = sb2[2 * 32];
    float2 e2p = sb2[3 * 32];
    float2 e3p = sb2[4 * 32];

#pragma unroll 1
    for (int t = 1; t <= NT - 7; t += 4) {   // covers t = 1..1020
        CRF_STEP(0, e0p, 1); e0p = sb2[(size_t)(t + 4) * 32];
        CRF_STEP(1, e1p, 0); e1p = sb2[(size_t)(t + 5) * 32];
        CRF_STEP(0, e2p, 0); e2p = sb2[(size_t)(t + 6) * 32];
        CRF_STEP(1, e3p, 0); e3p = (t + 7 <= NT - 1)
                                   ? sb2[(size_t)(t + 7) * 32]
                                   : make_float2(0.f, 0.f);
    }
    CRF_STEP(0, e0p, 0);   // t = 1021
    CRF_STEP(1, e1p, 0);   // t = 1022
    CRF_STEP(0, e2p, 0);   // t = 1023

    // normalizer = Mac + log( sum_o u[o] * e^{end[o]} )
    const float wv = u0r * __expf(endv[o0]) + u1r * __expf(endv[o1]);
    const float s = warp_sum(wv);
    if (l == 0)
        g_norm[b] = (float)(Mac + (double)__logf(s));
}

__global__ void crf_reduce_kernel(float* __restrict__ out) {
    __shared__ float w[8];
    const int i = threadIdx.x;
    float v = g_norm[i] - g_gold2[0][i] - g_gold2[1][i];
#pragma unroll
    for (int k = 16; k; k >>= 1) v += __shfl_xor_sync(0xffffffffu, v, k);
    if ((i & 31) == 0) w[i >> 5] = v;
    __syncthreads();
    if (i == 0) {
        float s = 0.0f;
#pragma unroll
        for (int k = 0; k < 8; k++) s += w[k];
        out[0] = s * (1.0f / (float)NB);
    }
}

extern "C" void kernel_launch(void* const* d_in, const int* in_sizes, int n_in,
                              void* d_out, int out_size)
{
    const float* scores  = (const float*)d_in[0];
    const int*   targets = (const int*)d_in[1];
    const float* startv  = (const float*)d_in[2];
    const float* Tmat    = (const float*)d_in[3];
    const float* endv    = (const float*)d_in[4];

    crf_main_kernel<<<34, 256>>>(scores, targets, startv, Tmat, endv);
    crf_reduce_kernel<<<1, NB>>>((float*)d_out);
}

// round 12
// speedup vs baseline: 1.5777x; 1.4776x over previous
#include <cuda_runtime.h>

#define NB 256
#define NT 1024
#define NL 64

__device__ float g_norm[NB];
__device__ float g_gold2[2][NB];

__device__ __forceinline__ float warp_sum(float v) {
#pragma unroll
    for (int k = 16; k; k >>= 1) v += __shfl_xor_sync(0xffffffffu, v, k);
    return v;
}

// One scan step. Lane owns ONE output state o. Reads full u(t-1) (64 floats) from
// uch[RD], accumulates a scalar dot product via 32 FFMA2 into 4 accumulators,
// writes u(t)[o] to uch[RD^1][o]. One __syncthreads (shared by both chains in the
// CTA) both orders the exchange and drains the STS.
#define CRF_STEP(RD, eraw, RESC) do {                                                  \
    const float ee_ = __expf(eraw);                                                    \
    const float* rbuf_ = uch[(RD)];                                                    \
    float r_ = 1.0f;                                                                   \
    if (RESC) {                                                                        \
        const float u0_ = rbuf_[0];                                                    \
        asm("rcp.approx.f32 %0, %1;" : "=f"(r_) : "f"(u0_));                           \
        Mac += (double)__logf(u0_);                                                    \
    }                                                                                  \
    unsigned long long a0_ = 0ull, a1_ = 0ull, a2_ = 0ull, a3_ = 0ull;                 \
    const ulonglong2* rp_ = (const ulonglong2*)rbuf_;                                  \
    _Pragma("unroll")                                                                  \
    for (int j_ = 0; j_ < 16; j_++) {                                                  \
        const ulonglong2 v_ = rp_[j_];                                                 \
        if (j_ & 1) {                                                                  \
            asm("fma.rn.f32x2 %0, %1, %2, %0;" : "+l"(a2_) : "l"(v_.x), "l"(Ec[2*j_]));   \
            asm("fma.rn.f32x2 %0, %1, %2, %0;" : "+l"(a3_) : "l"(v_.y), "l"(Ec[2*j_+1])); \
        } else {                                                                       \
            asm("fma.rn.f32x2 %0, %1, %2, %0;" : "+l"(a0_) : "l"(v_.x), "l"(Ec[2*j_]));   \
            asm("fma.rn.f32x2 %0, %1, %2, %0;" : "+l"(a1_) : "l"(v_.y), "l"(Ec[2*j_+1])); \
        }                                                                              \
    }                                                                                  \
    asm("add.rn.f32x2 %0, %0, %1;" : "+l"(a0_) : "l"(a1_));                            \
    asm("add.rn.f32x2 %0, %0, %1;" : "+l"(a2_) : "l"(a3_));                            \
    asm("add.rn.f32x2 %0, %0, %1;" : "+l"(a0_) : "l"(a2_));                            \
    float lo_, hi_;                                                                    \
    asm("mov.b64 {%0, %1}, %2;" : "=f"(lo_), "=f"(hi_) : "l"(a0_));                    \
    u = RESC ? ((lo_ + hi_) * ee_ * r_) : ((lo_ + hi_) * ee_);                         \
    uch[(RD) ^ 1][o] = u;                                                              \
    __syncthreads();                                                                   \
} while (0)

__global__ __launch_bounds__(128, 1) void crf_main_kernel(
    const float* __restrict__ scores, const int* __restrict__ targets,
    const float* __restrict__ startv, const float* __restrict__ Tmat,
    const float* __restrict__ endv)
{
    // ---- gold-path CTAs (blockIdx 128..131): 512 half-chains, one per thread ----
    if (blockIdx.x >= NB / 2) {
        const int idx  = (blockIdx.x - NB / 2) * 128 + threadIdx.x;  // 0..511
        const int b    = idx & (NB - 1);
        const int half = idx >> 8;
        const int*   tg = targets + (size_t)b * NT;
        const float* sc = scores + (size_t)b * NT * NL;
        float g; int tp, tbeg;
        if (half == 0) { tp = tg[0]; g = startv[tp] + sc[tp]; tbeg = 1; }
        else           { tp = tg[NT / 2 - 1]; g = 0.0f; tbeg = NT / 2; }
        const int tend = half ? NT : NT / 2;
#pragma unroll 8
        for (int t = tbeg; t < tend; t++) {
            const int c = tg[t];
            g += sc[(size_t)t * NL + c] + Tmat[c * NL + tp];
            tp = c;
        }
        if (half) g += endv[tp];
        g_gold2[half][b] = g;
        return;
    }

    // ---- forward CTAs: 2 chains x 2 warps; every SMSP hosts exactly 1 warp ----
    __shared__ __align__(16) float usm[2][2][NL];   // [chain][parity][state]
    __shared__ float fin[2][2];                      // [chain][warp-in-pair]

    const int tid = threadIdx.x;
    const int ch  = tid >> 6;            // chain within CTA (0/1)
    const int wp  = (tid >> 5) & 1;      // warp within chain pair
    const int l   = tid & 31;
    const int o   = wp * 32 + l;         // the ONE output state this lane owns
    const int b   = blockIdx.x * 2 + ch;
    float (*uch)[NL] = usm[ch];

    // E row for this lane's output state: Ec[j] packs (E[o][2j], E[o][2j+1])
    unsigned long long Ec[32];
#pragma unroll
    for (int j = 0; j < 32; j++) {
        const float a0 = __expf(__ldg(&Tmat[o * NL + 2 * j]));
        const float a1 = __expf(__ldg(&Tmat[o * NL + 2 * j + 1]));
        asm("mov.b64 %0, {%1, %2};" : "=l"(Ec[j]) : "f"(a0), "f"(a1));
    }

    // ---- t = 0 init: anchor = prev0[state 0] = startv[0] + scores[b,0,0] ----
    const float* sb = scores + (size_t)b * NT * NL + o;
    const float emit0 = sb[0];
    const float m0 = __ldg(&startv[0]) + __ldg(&scores[(size_t)b * NT * NL]);
    double Mac = (double)m0;
    float u = __expf(startv[o] + emit0 - m0);
    uch[0][o] = u;                        // buf 0 = u(0)
    __syncthreads();

    // emit prefetch, depth 4 (one scalar LDG per step per lane)
    float e0r = sb[1 * NL];
    float e1r = sb[2 * NL];
    float e2r = sb[3 * NL];
    float e3r = sb[4 * NL];

#pragma unroll 1
    for (int t = 1; t <= NT - 7; t += 4) {   // covers t = 1..1020
        CRF_STEP(0, e0r, 1); e0r = sb[(size_t)(t + 4) * NL];
        CRF_STEP(1, e1r, 0); e1r = sb[(size_t)(t + 5) * NL];
        CRF_STEP(0, e2r, 0); e2r = sb[(size_t)(t + 6) * NL];
        CRF_STEP(1, e3r, 0); e3r = (t + 7 <= NT - 1) ? sb[(size_t)(t + 7) * NL] : 0.0f;
    }
    CRF_STEP(0, e0r, 0);   // t = 1021
    CRF_STEP(1, e1r, 0);   // t = 1022
    CRF_STEP(0, e2r, 0);   // t = 1023

    // ---- finalize: normalizer = Mac + log( sum_o u[o] * e^{end[o]} ) ----
    const float wv = u * __expf(endv[o]);
    const float s = warp_sum(wv);         // 32 states of this warp
    if (l == 0) fin[ch][wp] = s;
    __syncthreads();
    if (wp == 0 && l == 0)
        g_norm[b] = (float)(Mac + (double)__logf(fin[ch][0] + fin[ch][1]));
}

__global__ void crf_reduce_kernel(float* __restrict__ out) {
    __shared__ float w[8];
    const int i = threadIdx.x;
    float v = g_norm[i] - g_gold2[0][i] - g_gold2[1][i];
#pragma unroll
    for (int k = 16; k; k >>= 1) v += __shfl_xor_sync(0xffffffffu, v, k);
    if ((i & 31) == 0) w[i >> 5] = v;
    __syncthreads();
    if (i == 0) {
        float s = 0.0f;
#pragma unroll
        for (int k = 0; k < 8; k++) s += w[k];
        out[0] = s * (1.0f / (float)NB);
    }
}

extern "C" void kernel_launch(void* const* d_in, const int* in_sizes, int n_in,
                              void* d_out, int out_size)
{
    const float* scores  = (const float*)d_in[0];
    const int*   targets = (const int*)d_in[1];
    const float* startv  = (const float*)d_in[2];
    const float* Tmat    = (const float*)d_in[3];
    const float* endv    = (const float*)d_in[4];

    crf_main_kernel<<<NB / 2 + 4, 128>>>(scores, targets, startv, Tmat, endv);
    crf_reduce_kernel<<<1, NB>>>((float*)d_out);
}

// round 13
// speedup vs baseline: 2.5853x; 1.6386x over previous
#include <cuda_runtime.h>

#define NB 256
#define NT 1024
#define NL 64

__device__ float g_norm[NB];
__device__ float g_gold2[2][NB];

__device__ __forceinline__ float warp_sum(float v) {
#pragma unroll
    for (int k = 16; k; k >>= 1) v += __shfl_xor_sync(0xffffffffu, v, k);
    return v;
}

// One scan step, intra-warp (R6 structure). Reads u(prev) from buf[RD], writes
// u(new) to buf[RD^1]. Lane owns states 2l, 2l+1; E rows (or columns, for the
// backward direction) live in regs as f32x2 pairs. RESC: rescale by 1/u[0].
#define CRF_STEP(RD, eraw, RESC) do {                                                  \
    const float ee0_ = __expf((eraw).x);                                               \
    const float ee1_ = __expf((eraw).y);                                               \
    const float* rbuf_ = uch[(RD)];                                                    \
    float r_ = 1.0f;                                                                   \
    if (RESC) {                                                                        \
        const float u0_ = rbuf_[0];                                                    \
        asm("rcp.approx.f32 %0, %1;" : "=f"(r_) : "f"(u0_));                           \
        Mac += (double)__logf(u0_);                                                    \
    }                                                                                  \
    unsigned long long a0_ = 0ull, a1_ = 0ull, a2_ = 0ull, a3_ = 0ull;                 \
    const ulonglong2* rp_ = (const ulonglong2*)rbuf_;                                  \
    _Pragma("unroll")                                                                  \
    for (int j_ = 0; j_ < 16; j_++) {                                                  \
        const ulonglong2 v_ = rp_[j_];                                                 \
        asm("fma.rn.f32x2 %0, %1, %2, %0;" : "+l"(a0_) : "l"(v_.x), "l"(E0[2*j_]));    \
        asm("fma.rn.f32x2 %0, %1, %2, %0;" : "+l"(a1_) : "l"(v_.y), "l"(E0[2*j_+1]));  \
        asm("fma.rn.f32x2 %0, %1, %2, %0;" : "+l"(a2_) : "l"(v_.x), "l"(E1[2*j_]));    \
        asm("fma.rn.f32x2 %0, %1, %2, %0;" : "+l"(a3_) : "l"(v_.y), "l"(E1[2*j_+1]));  \
    }                                                                                  \
    asm("add.rn.f32x2 %0, %0, %1;" : "+l"(a0_) : "l"(a1_));                            \
    asm("add.rn.f32x2 %0, %0, %1;" : "+l"(a2_) : "l"(a3_));                            \
    float x0_, y0_, x1_, y1_;                                                          \
    asm("mov.b64 {%0, %1}, %2;" : "=f"(x0_), "=f"(y0_) : "l"(a0_));                    \
    asm("mov.b64 {%0, %1}, %2;" : "=f"(x1_), "=f"(y1_) : "l"(a2_));                    \
    if (RESC) { u0r = (x0_ + y0_) * ee0_ * r_; u1r = (x1_ + y1_) * ee1_ * r_; }        \
    else      { u0r = (x0_ + y0_) * ee0_;      u1r = (x1_ + y1_) * ee1_; }             \
    unsigned long long up_;                                                            \
    asm("mov.b64 %0, {%1, %2};" : "=l"(up_) : "f"(u0r), "f"(u1r));                     \
    ((unsigned long long*)uch[(RD) ^ 1])[l] = up_;                                     \
    __syncwarp();                                                                      \
} while (0)

__global__ __launch_bounds__(128, 1) void crf_main_kernel(
    const float* __restrict__ scores, const int* __restrict__ targets,
    const float* __restrict__ startv, const float* __restrict__ Tmat,
    const float* __restrict__ endv)
{
    // ---- gold-path CTAs (blockIdx 128..131): 512 half-chains ----
    if (blockIdx.x >= NB / 2) {
        const int idx  = (blockIdx.x - NB / 2) * 128 + threadIdx.x;  // 0..511
        const int b    = idx & (NB - 1);
        const int half = idx >> 8;
        const int*   tg = targets + (size_t)b * NT;
        const float* sc = scores + (size_t)b * NT * NL;
        float g; int tp, tbeg;
        if (half == 0) { tp = tg[0]; g = startv[tp] + sc[tp]; tbeg = 1; }
        else           { tp = tg[NT / 2 - 1]; g = 0.0f; tbeg = NT / 2; }
        const int tend = half ? NT : NT / 2;
#pragma unroll 8
        for (int t = tbeg; t < tend; t++) {
            const int c = tg[t];
            g += sc[(size_t)t * NL + c] + Tmat[c * NL + tp];
            tp = c;
        }
        if (half) g += endv[tp];
        g_gold2[half][b] = g;
        return;
    }

    // ---- forward CTAs: warp = (batch, direction); depth 512 each way ----
    __shared__ __align__(16) float usm[4][2][NL];   // [warp][parity][state]
    __shared__ __align__(16) float bfin[2][NL];     // bwd final beta, per batch
    __shared__ double bmac[2];                      // bwd Mac, per batch

    const int tid = threadIdx.x;
    const int w   = tid >> 5;            // warp -> SMSP w%4 (one warp each)
    const int ch  = w >> 1;              // batch within CTA
    const int dir = w & 1;               // 0 = forward (alpha), 1 = backward (beta)
    const int l   = tid & 31;
    const int b   = blockIdx.x * 2 + ch;
    const int o0  = 2 * l, o1 = 2 * l + 1;
    float (*uch)[NL] = usm[w];

    // E pairs: fwd lane needs row o of T_mat (alpha: sum_p e^{T[o][p]} u[p]);
    // bwd lane needs column o (beta: sum_c e^{T[c][o]} w[c]).
    unsigned long long E0[32], E1[32];
    if (dir == 0) {
#pragma unroll
        for (int j = 0; j < 32; j++) {
            const float a0 = __expf(__ldg(&Tmat[o0 * NL + 2 * j]));
            const float a1 = __expf(__ldg(&Tmat[o0 * NL + 2 * j + 1]));
            asm("mov.b64 %0, {%1, %2};" : "=l"(E0[j]) : "f"(a0), "f"(a1));
            const float c0 = __expf(__ldg(&Tmat[o1 * NL + 2 * j]));
            const float c1 = __expf(__ldg(&Tmat[o1 * NL + 2 * j + 1]));
            asm("mov.b64 %0, {%1, %2};" : "=l"(E1[j]) : "f"(c0), "f"(c1));
        }
    } else {
#pragma unroll
        for (int j = 0; j < 32; j++) {
            const float a0 = __expf(__ldg(&Tmat[(2 * j) * NL + o0]));
            const float a1 = __expf(__ldg(&Tmat[(2 * j + 1) * NL + o0]));
            asm("mov.b64 %0, {%1, %2};" : "=l"(E0[j]) : "f"(a0), "f"(a1));
            const float c0 = __expf(__ldg(&Tmat[(2 * j) * NL + o1]));
            const float c1 = __expf(__ldg(&Tmat[(2 * j + 1) * NL + o1]));
            asm("mov.b64 %0, {%1, %2};" : "=l"(E1[j]) : "f"(c0), "f"(c1));
        }
    }

    const float2* sb2 = reinterpret_cast<const float2*>(scores + (size_t)b * NT * NL) + l;
    double Mac;
    float u0r, u1r;

    if (dir == 0) {
        // ================= forward: alpha_0 .. alpha_512 (512 steps) ==========
        const float2 em0 = sb2[0];
        const float p0x = startv[o0] + em0.x;
        const float p0y = startv[o1] + em0.y;
        const float m0  = __ldg(&startv[0]) + __ldg(&scores[(size_t)b * NT * NL]);
        Mac = (double)m0;
        u0r = __expf(p0x - m0);
        u1r = __expf(p0y - m0);
        {
            unsigned long long up;
            asm("mov.b64 %0, {%1, %2};" : "=l"(up) : "f"(u0r), "f"(u1r));
            ((unsigned long long*)uch[0])[l] = up;
        }
        __syncwarp();

        float2 e0p = sb2[1 * 32], e1p = sb2[2 * 32], e2p = sb2[3 * 32], e3p = sb2[4 * 32];

#pragma unroll 1
        for (int t = 1; t <= 505; t += 4) {   // 127 iters: steps 1..508
            CRF_STEP(0, e0p, 1); e0p = sb2[(size_t)(t + 4) * 32];
            CRF_STEP(1, e1p, 0); e1p = sb2[(size_t)(t + 5) * 32];
            CRF_STEP(0, e2p, 0); e2p = sb2[(size_t)(t + 6) * 32];
            CRF_STEP(1, e3p, 0); e3p = sb2[(size_t)(t + 7) * 32];
        }
        CRF_STEP(0, e0p, 1);   // t = 509
        CRF_STEP(1, e1p, 0);   // t = 510
        CRF_STEP(0, e2p, 0);   // t = 511
        CRF_STEP(1, e3p, 0);   // t = 512  -> lane holds alpha_512 (scaled)
    } else {
        // ============ backward: w_t = ee_t ⊙ (E^T w_{t+1}); 511 steps ==========
        // init w_1023 = exp(end + emit_1023 - m0b); steps consume emits 1022..513,
        // final step uses ee = 1 producing beta_512.
        const float2 emL = sb2[(size_t)(NT - 1) * 32];
        const float q0x = endv[o0] + emL.x;
        const float q0y = endv[o1] + emL.y;
        const float m0b = __ldg(&endv[0]) + __ldg(&scores[((size_t)b * NT + NT - 1) * NL]);
        Mac = (double)m0b;
        u0r = __expf(q0x - m0b);
        u1r = __expf(q0y - m0b);
        {
            unsigned long long up;
            asm("mov.b64 %0, {%1, %2};" : "=l"(up) : "f"(u0r), "f"(u1r));
            ((unsigned long long*)uch[0])[l] = up;
        }
        __syncwarp();

        // step s (s=0..510) reads buf[s&1]; s<=509 uses emit t=1022-s; s=510 -> ee=1
        float2 e0p = sb2[(size_t)1022 * 32], e1p = sb2[(size_t)1021 * 32];
        float2 e2p = sb2[(size_t)1020 * 32], e3p = sb2[(size_t)1019 * 32];
        const float2 zz = make_float2(0.f, 0.f);

#pragma unroll 1
        for (int s = 0; s <= 504; s += 4) {   // 127 iters: steps 0..507
            CRF_STEP(0, e0p, 1);
            e0p = (s + 4 <= 509) ? sb2[(size_t)(1022 - (s + 4)) * 32] : zz;
            CRF_STEP(1, e1p, 0);
            e1p = (s + 5 <= 509) ? sb2[(size_t)(1022 - (s + 5)) * 32] : zz;
            CRF_STEP(0, e2p, 0);
            e2p = (s + 6 <= 509) ? sb2[(size_t)(1022 - (s + 6)) * 32] : zz;
            CRF_STEP(1, e3p, 0);
            e3p = (s + 7 <= 509) ? sb2[(size_t)(1022 - (s + 7)) * 32] : zz;
        }
        CRF_STEP(0, e0p, 1);   // s = 508 (t = 514)
        CRF_STEP(1, e1p, 0);   // s = 509 (t = 513)
        CRF_STEP(0, e2p, 0);   // s = 510: e2p = (0,0) -> ee = 1 -> beta_512
    }

    // ---- combine: Z_b = Mac_f + Mac_b + log( sum_j alpha512[j] * beta512[j] ) ----
    if (dir == 1) {
        bfin[ch][o0] = u0r;
        bfin[ch][o1] = u1r;
        if (l == 0) bmac[ch] = Mac;
    }
    __syncthreads();
    if (dir == 0) {
        const float v = u0r * bfin[ch][o0] + u1r * bfin[ch][o1];
        const float s = warp_sum(v);
        if (l == 0)
            g_norm[b] = (float)(Mac + bmac[ch] + (double)__logf(s));
    }
}

__global__ void crf_reduce_kernel(float* __restrict__ out) {
    __shared__ float w[8];
    const int i = threadIdx.x;
    float v = g_norm[i] - g_gold2[0][i] - g_gold2[1][i];
#pragma unroll
    for (int k = 16; k; k >>= 1) v += __shfl_xor_sync(0xffffffffu, v, k);
    if ((i & 31) == 0) w[i >> 5] = v;
    __syncthreads();
    if (i == 0) {
        float s = 0.0f;
#pragma unroll
        for (int k = 0; k < 8; k++) s += w[k];
        out[0] = s * (1.0f / (float)NB);
    }
}

extern "C" void kernel_launch(void* const* d_in, const int* in_sizes, int n_in,
                              void* d_out, int out_size)
{
    const float* scores  = (const float*)d_in[0];
    const int*   targets = (const int*)d_in[1];
    const float* startv  = (const float*)d_in[2];
    const float* Tmat    = (const float*)d_in[3];
    const float* endv    = (const float*)d_in[4];

    crf_main_kernel<<<NB / 2 + 4, 128>>>(scores, targets, startv, Tmat, endv);
    crf_reduce_kernel<<<1, NB>>>((float*)d_out);
}